// round 8
// baseline (speedup 1.0000x reference)
#include <cuda_runtime.h>
#include <cuda_bf16.h>
#include <mma.h>

using namespace nvcuda;

#define B_DIM 128
#define K_DIM 2048
#define D_DIM 512

// GEMM tiling
#define BM 64               // batch rows per block
#define BN 16               // k cols per block
#define DC 64               // d per pipeline stage
#define NSTAGE (D_DIM / DC) // 8
#define PITCH 72            // bf16 elems per smem row (64 + 8 pad) = 144B
#define THREADS 256

// dynamic smem layout (bytes)
#define XH_OFF 0            // [2][64][PITCH] bf16 = 18432
#define XL_OFF 18432
#define PH_OFF 36864        // [2][16][PITCH] bf16 = 4608
#define PL_OFF 41472
#define AH_OFF 46080
#define AL_OFF 50688
#define C_OFF  55296        // 8 warps x 16x16 f32 = 8192 (P: 0..1023, A: 1024..2047)
#define SMEM_BYTES 63488

// ---------------------------------------------------------------------------
// Device-global scratch (no cudaMalloc allowed)
// ---------------------------------------------------------------------------
__device__ float g_uu[K_DIM];
__device__ float g_ua[K_DIM];
__device__ float g_a2[K_DIM];
__device__ float g_vv[B_DIM];
__device__ __nv_bfloat16 g_ph[K_DIM * D_DIM];
__device__ __nv_bfloat16 g_pl[K_DIM * D_DIM];
__device__ __nv_bfloat16 g_ah[K_DIM * D_DIM];
__device__ __nv_bfloat16 g_al[K_DIM * D_DIM];
__device__ __nv_bfloat16 g_xh[B_DIM * D_DIM];
__device__ __nv_bfloat16 g_xl[B_DIM * D_DIM];

struct __align__(8) bh4 { __nv_bfloat162 a, b; };

__device__ __forceinline__ void split4(float4 v, __nv_bfloat16* hi,
                                       __nv_bfloat16* lo, int idx) {
    __nv_bfloat16 h0 = __float2bfloat16_rn(v.x);
    __nv_bfloat16 h1 = __float2bfloat16_rn(v.y);
    __nv_bfloat16 h2 = __float2bfloat16_rn(v.z);
    __nv_bfloat16 h3 = __float2bfloat16_rn(v.w);
    bh4 H; H.a = __nv_bfloat162(h0, h1); H.b = __nv_bfloat162(h2, h3);
    *(bh4*)(hi + idx) = H;
    bh4 L;
    L.a = __nv_bfloat162(__float2bfloat16_rn(v.x - __bfloat162float(h0)),
                         __float2bfloat16_rn(v.y - __bfloat162float(h1)));
    L.b = __nv_bfloat162(__float2bfloat16_rn(v.z - __bfloat162float(h2)),
                         __float2bfloat16_rn(v.w - __bfloat162float(h3)));
    *(bh4*)(lo + idx) = L;
}

// ---------------------------------------------------------------------------
// Kernel 1: per-row stats (fp32) + bf16 hi/lo split of p, a, x.
// ---------------------------------------------------------------------------
__global__ void stats_split_kernel(const float* __restrict__ inp,
                                   const float* __restrict__ p,
                                   const float* __restrict__ a) {
    int warp = (blockIdx.x * blockDim.x + threadIdx.x) >> 5;
    int lane = threadIdx.x & 31;

    if (warp < K_DIM) {
        const float4* pr = (const float4*)(p + warp * D_DIM);
        const float4* ar = (const float4*)(a + warp * D_DIM);
        float pp = 0.f, pa = 0.f, aa = 0.f;
#pragma unroll
        for (int i = 0; i < D_DIM / 128; i++) {
            float4 pv = pr[lane + i * 32];
            float4 av = ar[lane + i * 32];
            pp += pv.x * pv.x + pv.y * pv.y + pv.z * pv.z + pv.w * pv.w;
            pa += pv.x * av.x + pv.y * av.y + pv.z * av.z + pv.w * av.w;
            aa += av.x * av.x + av.y * av.y + av.z * av.z + av.w * av.w;
            int idx = warp * D_DIM + (lane + i * 32) * 4;
            split4(pv, g_ph, g_pl, idx);
            split4(av, g_ah, g_al, idx);
        }
#pragma unroll
        for (int off = 16; off > 0; off >>= 1) {
            pp += __shfl_xor_sync(0xFFFFFFFFu, pp, off);
            pa += __shfl_xor_sync(0xFFFFFFFFu, pa, off);
            aa += __shfl_xor_sync(0xFFFFFFFFu, aa, off);
        }
        if (lane == 0) {
            g_uu[warp] = pp;
            g_ua[warp] = -pa;
            g_a2[warp] = aa;
        }
    } else if (warp < K_DIM + B_DIM) {
        int b = warp - K_DIM;
        const float4* xr = (const float4*)(inp + b * D_DIM);
        float vv = 0.f;
#pragma unroll
        for (int i = 0; i < D_DIM / 128; i++) {
            float4 xv = xr[lane + i * 32];
            vv += xv.x * xv.x + xv.y * xv.y + xv.z * xv.z + xv.w * xv.w;
            split4(xv, g_xh, g_xl, b * D_DIM + (lane + i * 32) * 4);
        }
#pragma unroll
        for (int off = 16; off > 0; off >>= 1)
            vv += __shfl_xor_sync(0xFFFFFFFFu, vv, off);
        if (lane == 0) g_vv[b] = vv;
    }
}

// cp.async helpers
__device__ __forceinline__ void cp16(void* dst, const void* src) {
    unsigned saddr = (unsigned)__cvta_generic_to_shared(dst);
    asm volatile("cp.async.cg.shared.global [%0], [%1], 16;\n"
                 :: "r"(saddr), "l"(src));
}
__device__ __forceinline__ void cp_commit() {
    asm volatile("cp.async.commit_group;\n" ::: "memory");
}
__device__ __forceinline__ void cp_wait1() {
    asm volatile("cp.async.wait_group 1;\n" ::: "memory");
}
__device__ __forceinline__ void cp_wait0() {
    asm volatile("cp.async.wait_group 0;\n" ::: "memory");
}

// ---------------------------------------------------------------------------
// Kernel 2: bf16 WMMA dual GEMM (3-term fp32-emulation) + MLR epilogue.
// Grid: (K/BN, B/BM) = (128, 2) = 256 blocks, 256 threads (8 warps).
// Warp pairing: warps 0-3 compute fP for b-rows [16w,16w+16); warps 4-7
// compute fA for the same rows. Each warp: 3 mmas per 16-d chunk.
// ---------------------------------------------------------------------------
__global__ __launch_bounds__(THREADS, 2)
void hyper_logits_wmma(float* __restrict__ out) {
    extern __shared__ __align__(16) char sm[];
    __nv_bfloat16* XH = (__nv_bfloat16*)(sm + XH_OFF);
    __nv_bfloat16* XL = (__nv_bfloat16*)(sm + XL_OFF);
    __nv_bfloat16* PH = (__nv_bfloat16*)(sm + PH_OFF);
    __nv_bfloat16* PL = (__nv_bfloat16*)(sm + PL_OFF);
    __nv_bfloat16* AH = (__nv_bfloat16*)(sm + AH_OFF);
    __nv_bfloat16* AL = (__nv_bfloat16*)(sm + AL_OFF);
    float* C = (float*)(sm + C_OFF);

    const int tid = threadIdx.x;
    const int warp = tid >> 5;
    const int mat = warp >> 2;          // 0: P-GEMM, 1: A-GEMM
    const int wb = warp & 3;            // b-row group (16 rows each)
    const int kbase = blockIdx.x * BN;
    const int bbase = blockIdx.y * BM;

    // ---- stage copy: 6 cp16 per thread ----
    auto copy_stage = [&](int s, int d0) {
        // X: 64 rows x 64 cols, hi+lo (512 cp16 each)
#pragma unroll
        for (int j = 0; j < 2; j++) {
            int id = tid + 256 * j;                 // 0..511
            int row = id >> 3, c8 = (id & 7) * 8;
            size_t goff = (size_t)(bbase + row) * D_DIM + d0 + c8;
            cp16(XH + (s * 64 + row) * PITCH + c8, g_xh + goff);
            cp16(XL + (s * 64 + row) * PITCH + c8, g_xl + goff);
        }
        // weights: 4 arrays x 128 cp16
        {
            int arr = tid >> 7, r = tid & 127;
            int row = r >> 3, c8 = (r & 7) * 8;
            size_t goff = (size_t)(kbase + row) * D_DIM + d0 + c8;
            int so = (s * 16 + row) * PITCH + c8;
            if (arr == 0) {
                cp16(PH + so, g_ph + goff);
                cp16(AH + so, g_ah + goff);
            } else {
                cp16(PL + so, g_pl + goff);
                cp16(AL + so, g_al + goff);
            }
        }
    };

    wmma::fragment<wmma::accumulator, 16, 16, 16, float> acc;
    wmma::fill_fragment(acc, 0.0f);

    const __nv_bfloat16* BH = mat ? AH : PH;
    const __nv_bfloat16* BL = mat ? AL : PL;

    copy_stage(0, 0);
    cp_commit();

    for (int t = 0; t < NSTAGE; t++) {
        if (t + 1 < NSTAGE) {
            copy_stage((t + 1) & 1, (t + 1) * DC);
            cp_commit();
            cp_wait1();
        } else {
            cp_wait0();
        }
        __syncthreads();

        const int s = t & 1;
        const __nv_bfloat16* xh = XH + (s * 64 + wb * 16) * PITCH;
        const __nv_bfloat16* xl = XL + (s * 64 + wb * 16) * PITCH;
        const __nv_bfloat16* bh = BH + s * 16 * PITCH;
        const __nv_bfloat16* bl = BL + s * 16 * PITCH;

#pragma unroll
        for (int cc = 0; cc < DC / 16; cc++) {
            const int dcol = cc * 16;
            wmma::fragment<wmma::matrix_a, 16, 16, 16, __nv_bfloat16,
                           wmma::row_major> aH, aL;
            wmma::fragment<wmma::matrix_b, 16, 16, 16, __nv_bfloat16,
                           wmma::col_major> fBH, fBL;
            wmma::load_matrix_sync(aH, xh + dcol, PITCH);
            wmma::load_matrix_sync(aL, xl + dcol, PITCH);
            wmma::load_matrix_sync(fBH, bh + dcol, PITCH);
            wmma::load_matrix_sync(fBL, bl + dcol, PITCH);

            wmma::mma_sync(acc, aH, fBH, acc);
            wmma::mma_sync(acc, aL, fBH, acc);
            wmma::mma_sync(acc, aH, fBL, acc);
        }
        __syncthreads();
    }

    // ---- dump accumulators: P -> C[0..1023], A -> C[1024..2047] ----
    wmma::store_matrix_sync(C + mat * 1024 + wb * 256, acc, 16,
                            wmma::mem_row_major);
    __syncthreads();

    // ---- epilogue: 64 rows x 16 cols = 1024 logits, 4 per thread ----
#pragma unroll
    for (int i = 0; i < 4; i++) {
        int idx = tid + 256 * i;                    // 0..1023
        int r = idx >> 4;                           // local b row 0..63
        int c = idx & 15;                           // local k col
        const int b = bbase + r;
        const int k = kbase + c;

        float xp = C[idx];
        float xa = C[1024 + idx];

        const float uu = g_uu[k];
        const float ua = g_ua[k];
        const float an = sqrtf(g_a2[k]);
        const float coef = 2.0f / (1.0f - uu) * an;
        const float beta = 1.0f - uu;
        const float vv = g_vv[b];

        float uv = -xp;                             // <u,x> = -<p,x>
        float alpha = 1.0f + 2.0f * uv + vv;
        float den   = 1.0f + 2.0f * uv + uu * vv;
        float inv   = 1.0f / den;
        float wa = (alpha * ua + beta * xa) * inv;
        float ww = (alpha * alpha * uu + 2.0f * alpha * beta * uv
                    + beta * beta * vv) * (inv * inv);
        out[b * K_DIM + k] = coef * asinhf(2.0f * wa / (an * (1.0f - ww)));
    }
}

// ---------------------------------------------------------------------------
extern "C" void kernel_launch(void* const* d_in, const int* in_sizes, int n_in,
                              void* d_out, int out_size) {
    const float* inp = (const float*)d_in[0];   // [B, D]
    const float* p   = (const float*)d_in[1];   // [K, D]
    const float* a   = (const float*)d_in[2];   // [K, D]
    float* out = (float*)d_out;                 // [B, K]

    static bool attr_set = false;
    if (!attr_set) {
        cudaFuncSetAttribute(hyper_logits_wmma,
                             cudaFuncAttributeMaxDynamicSharedMemorySize,
                             SMEM_BYTES);
        attr_set = true;
    }

    int nwarps = K_DIM + B_DIM;
    int blocks1 = (nwarps * 32 + 255) / 256;
    stats_split_kernel<<<blocks1, 256>>>(inp, p, a);

    dim3 grid(K_DIM / BN, B_DIM / BM);   // (128, 2) = 256 blocks
    hyper_logits_wmma<<<grid, THREADS, SMEM_BYTES>>>(out);
}